// round 6
// baseline (speedup 1.0000x reference)
#include <cuda_runtime.h>
#include <cuda_bf16.h>
#include <math.h>
#include <stdint.h>

#define NN    100000
#define EE    1600000
#define FIN   165
#define HH    128
#define CCLS  2
#define CHUNK 512
#define NB    ((NN + CHUNK - 1) / CHUNK)   // 196

// ---------------- static device scratch (no allocation allowed) ----------------
__device__ __align__(16) float g_deg [NN];
__device__ __align__(16) float g_dinv[NN];
__device__ __align__(16) float g_w   [EE];
__device__ __align__(16) int   g_src [EE];
__device__ __align__(16) int   g_dst [EE];

// CSR (sorted by dst)
__device__ __align__(16) int   g_cnt [NN];
__device__ __align__(16) int   g_tmp [NN];
__device__ __align__(16) int   g_ptr [NN + 1];
__device__ __align__(16) int   g_fill[NN];
__device__ __align__(16) int   g_bsum[NB];
__device__ __align__(16) int   g_boff[NB];
__device__ __align__(16) int   g_esrc[EE];
__device__ __align__(16) float g_ews [EE];

__device__ __align__(16) float g_A [NN * HH];   // x @ (W0 - W2)
__device__ __align__(16) float g_B [NN * HH];   // x @ W1, then B + 2*P(C)
__device__ __align__(16) float g_C [NN * HH];   // x @ W2
__device__ __align__(16) float g_Hb[NN * HH];   // layer-1 activation h

__device__ __align__(16) float g_Wcat1[FIN * 3 * HH];  // 165 x 384
__device__ __align__(16) float g_Wcat2[HH  * 3 * HH];  // 128 x 384

// ---------------- helpers ----------------
__device__ __forceinline__ uint32_t f2tf32(float v) {
    uint32_t r;
    asm("cvt.rna.tf32.f32 %0, %1;" : "=r"(r) : "f"(v));
    return r;
}
__device__ __forceinline__ void split_tf32(float v, uint32_t& hi, uint32_t& lo) {
    hi = f2tf32(v);
    lo = f2tf32(v - __uint_as_float(hi));
}
#define MMA_TF32(d, a0, a1, a2, a3, b0, b1) \
    asm volatile("mma.sync.aligned.m16n8k8.row.col.f32.tf32.tf32.f32 " \
        "{%0,%1,%2,%3}, {%4,%5,%6,%7}, {%8,%9}, {%0,%1,%2,%3};" \
        : "+f"((d)[0]), "+f"((d)[1]), "+f"((d)[2]), "+f"((d)[3]) \
        : "r"(a0), "r"(a1), "r"(a2), "r"(a3), "r"(b0), "r"(b1))

// ---------------- setup kernels ----------------
__global__ void k_zero(float* __restrict__ p, int n4) {
    int i = blockIdx.x * blockDim.x + threadIdx.x;
    if (i < n4) ((float4*)p)[i] = make_float4(0.f, 0.f, 0.f, 0.f);
}

__global__ void k_deg(const int* __restrict__ ei) {
    int e = blockIdx.x * blockDim.x + threadIdx.x;
    if (e >= EE) return;
    int s = ei[e];
    int d = ei[EE + e];
    if ((unsigned)s >= NN || (unsigned)d >= NN) { s = 0; d = 0; }
    g_src[e] = s;
    g_dst[e] = d;
    if (s != d) atomicAdd(&g_deg[s], 1.0f);
}

__global__ void k_dinv() {
    int i = blockIdx.x * blockDim.x + threadIdx.x;
    if (i >= NN) return;
    float d = g_deg[i];
    g_dinv[i] = (d > 0.f) ? rsqrtf(d) : 0.f;
}

__global__ void k_edgew() {
    int e = blockIdx.x * blockDim.x + threadIdx.x;
    if (e >= EE) return;
    int s = g_src[e], d = g_dst[e];
    float w = (s != d) ? (-g_dinv[s] * g_dinv[d]) : 0.f;
    g_w[e] = w;
    if (w != 0.f) atomicAdd(&g_cnt[d], 1);
}

__global__ void k_scanA() {
    __shared__ int s[CHUNK];
    int i = blockIdx.x * CHUNK + threadIdx.x;
    int v = (i < NN) ? g_cnt[i] : 0;
    s[threadIdx.x] = v;
    __syncthreads();
    for (int off = 1; off < CHUNK; off <<= 1) {
        int t = (threadIdx.x >= off) ? s[threadIdx.x - off] : 0;
        __syncthreads();
        s[threadIdx.x] += t;
        __syncthreads();
    }
    if (i < NN) g_tmp[i] = s[threadIdx.x];
    if (threadIdx.x == CHUNK - 1) g_bsum[blockIdx.x] = s[CHUNK - 1];
}

__global__ void k_scanB() {
    __shared__ int s[256];
    int v = (threadIdx.x < NB) ? g_bsum[threadIdx.x] : 0;
    s[threadIdx.x] = v;
    __syncthreads();
    for (int off = 1; off < 256; off <<= 1) {
        int t = (threadIdx.x >= off) ? s[threadIdx.x - off] : 0;
        __syncthreads();
        s[threadIdx.x] += t;
        __syncthreads();
    }
    if (threadIdx.x < NB) g_boff[threadIdx.x] = s[threadIdx.x] - v;
    if (threadIdx.x == NB - 1) g_ptr[NN] = s[threadIdx.x];
}

__global__ void k_scanC() {
    int i = blockIdx.x * CHUNK + threadIdx.x;
    if (i >= NN) return;
    int excl = g_boff[blockIdx.x] + g_tmp[i] - g_cnt[i];
    g_ptr[i]  = excl;
    g_fill[i] = excl;
}

__global__ void k_scatter() {
    int e = blockIdx.x * blockDim.x + threadIdx.x;
    if (e >= EE) return;
    float w = g_w[e];
    if (w == 0.f) return;
    int pos = atomicAdd(&g_fill[g_dst[e]], 1);
    g_esrc[pos] = g_src[e];
    g_ews[pos]  = w;
}

__global__ void k_wcat(const float* __restrict__ W, float* __restrict__ Wcat, int kdim) {
    int idx = blockIdx.x * blockDim.x + threadIdx.x;
    int tot = kdim * 3 * HH;
    if (idx >= tot) return;
    int f = idx / (3 * HH);
    int c = idx - f * (3 * HH);
    float v;
    if (c < HH)            v = W[f * HH + c] - W[2 * kdim * HH + f * HH + c];
    else if (c < 2 * HH)   v = W[kdim * HH + f * HH + (c - HH)];
    else                   v = W[2 * kdim * HH + f * HH + (c - 2 * HH)];
    Wcat[idx] = v;
}

// ---------------- tensor-core GEMM via portable mma.sync (tf32, 3-pass hi/lo) ----------------
// C[N x 384] = X[N x kreal] @ Wcat[kreal x 384]; CTA tile 128x64, grid (6, ceil(N/128)).
// Warp tile 32x32: 2 (m16) x 4 (n8) fragments. Accuracy: hi*hi + hi*lo + lo*hi.
__global__ void __launch_bounds__(256) k_mma_gemm(
        const float* __restrict__ X, int kreal, int nkb,
        const float* __restrict__ Wcat,
        float* __restrict__ o0, float* __restrict__ o1, float* __restrict__ o2) {
    __shared__ float As[128][17];
    __shared__ float Bs[16][72];

    int tid  = threadIdx.x;
    int wid  = tid >> 5;
    int lane = tid & 31;
    int wm   = wid >> 1;          // 0..3 : 32-row strip
    int wn   = wid & 1;           // 0..1 : 32-col strip
    int g    = lane >> 2;         // groupID 0..7
    int t    = lane & 3;          // thread-in-group 0..3

    int nb   = blockIdx.x;        // 0..5
    int row0 = blockIdx.y * 128;
    int n0   = nb * 64;           // column offset into 384

    float acc[2][4][4];
#pragma unroll
    for (int mi = 0; mi < 2; mi++)
#pragma unroll
        for (int ni = 0; ni < 4; ni++)
#pragma unroll
            for (int j = 0; j < 4; j++) acc[mi][ni][j] = 0.f;

    for (int kb = 0; kb < nkb; kb++) {
        int k0 = kb * 16;
        // A tile 128x16 (coalesced 16-wide rows)
#pragma unroll
        for (int it = 0; it < 8; it++) {
            int idx = tid + it * 256;
            int m = idx >> 4, kk = idx & 15;
            int gr = row0 + m, gk = k0 + kk;
            As[m][kk] = (gr < NN && gk < kreal) ? X[(size_t)gr * kreal + gk] : 0.f;
        }
        // B tile 16x64 (coalesced 64-wide rows)
#pragma unroll
        for (int it = 0; it < 4; it++) {
            int idx = tid + it * 256;
            int kk = idx >> 6, nn = idx & 63;
            int gk = k0 + kk;
            Bs[kk][nn] = (gk < kreal) ? Wcat[(size_t)gk * 384 + n0 + nn] : 0.f;
        }
        __syncthreads();

#pragma unroll
        for (int s = 0; s < 2; s++) {
            int ks = s * 8;
            // A fragments (2 m-tiles), hi/lo split
            uint32_t ah[2][4], al[2][4];
#pragma unroll
            for (int mi = 0; mi < 2; mi++) {
                int rb = wm * 32 + mi * 16;
                split_tf32(As[rb + g    ][ks + t    ], ah[mi][0], al[mi][0]);
                split_tf32(As[rb + g + 8][ks + t    ], ah[mi][1], al[mi][1]);
                split_tf32(As[rb + g    ][ks + t + 4], ah[mi][2], al[mi][2]);
                split_tf32(As[rb + g + 8][ks + t + 4], ah[mi][3], al[mi][3]);
            }
            // B fragments (4 n-tiles), hi/lo split
            uint32_t bh[4][2], bl[4][2];
#pragma unroll
            for (int ni = 0; ni < 4; ni++) {
                int nc = wn * 32 + ni * 8 + g;
                split_tf32(Bs[ks + t    ][nc], bh[ni][0], bl[ni][0]);
                split_tf32(Bs[ks + t + 4][nc], bh[ni][1], bl[ni][1]);
            }
#pragma unroll
            for (int mi = 0; mi < 2; mi++)
#pragma unroll
                for (int ni = 0; ni < 4; ni++) {
                    MMA_TF32(acc[mi][ni], ah[mi][0], ah[mi][1], ah[mi][2], ah[mi][3],
                             bh[ni][0], bh[ni][1]);
                    MMA_TF32(acc[mi][ni], ah[mi][0], ah[mi][1], ah[mi][2], ah[mi][3],
                             bl[ni][0], bl[ni][1]);
                    MMA_TF32(acc[mi][ni], al[mi][0], al[mi][1], al[mi][2], al[mi][3],
                             bh[ni][0], bh[ni][1]);
                }
        }
        __syncthreads();
    }

    // epilogue: split columns [0,128)|[128,256)|[256,384) across o0/o1/o2
    float* O = (nb < 2) ? o0 : ((nb < 4) ? o1 : o2);
    int cbase = (nb & 1) * 64 + wn * 32;
#pragma unroll
    for (int mi = 0; mi < 2; mi++) {
        int r = row0 + wm * 32 + mi * 16 + g;
#pragma unroll
        for (int ni = 0; ni < 4; ni++) {
            int c = cbase + ni * 8 + t * 2;
            if (r < NN)
                *(float2*)(O + (size_t)r * HH + c) = make_float2(acc[mi][ni][0], acc[mi][ni][1]);
            if (r + 8 < NN)
                *(float2*)(O + (size_t)(r + 8) * HH + c) = make_float2(acc[mi][ni][2], acc[mi][ni][3]);
        }
    }
}

// ---------------- CSR prop, one warp per node, fused epilogues ----------------
template <int MODE>
__global__ void __launch_bounds__(256) k_prop_csr(
        const float* __restrict__ X,
        const float* __restrict__ P0, const float* __restrict__ P1,
        const float* __restrict__ bias,
        const float* __restrict__ Wl, const float* __restrict__ bl,
        float* __restrict__ Y) {
    int node = blockIdx.x * 8 + (threadIdx.x >> 5);
    if (node >= NN) return;
    int lane = threadIdx.x & 31;
    int beg = g_ptr[node], end = g_ptr[node + 1];

    float4 acc = make_float4(0.f, 0.f, 0.f, 0.f);
#pragma unroll 4
    for (int i = beg; i < end; i++) {
        int   s  = g_esrc[i];
        float wt = g_ews[i];
        float4 v = *(const float4*)(X + (size_t)s * HH + lane * 4);
        acc.x += wt * v.x; acc.y += wt * v.y;
        acc.z += wt * v.z; acc.w += wt * v.w;
    }

    size_t o  = (size_t)node * 32 + lane;
    int    cb = lane * 4;

    if (MODE == 1) {
        float4 b = ((const float4*)P0)[o];
        b.x += 2.f * acc.x; b.y += 2.f * acc.y;
        b.z += 2.f * acc.z; b.w += 2.f * acc.w;
        ((float4*)Y)[o] = b;
    } else if (MODE == 2) {
        float4 a = ((const float4*)P0)[o];
        a.x = fmaxf(a.x + acc.x + bias[cb + 0], 0.f);
        a.y = fmaxf(a.y + acc.y + bias[cb + 1], 0.f);
        a.z = fmaxf(a.z + acc.z + bias[cb + 2], 0.f);
        a.w = fmaxf(a.w + acc.w + bias[cb + 3], 0.f);
        ((float4*)Y)[o] = a;
    } else {
        float4 h = ((const float4*)P0)[o];
        float4 a = ((const float4*)P1)[o];
        float h0 = h.x + a.x + acc.x + bias[cb + 0];
        float h1 = h.y + a.y + acc.y + bias[cb + 1];
        float h2 = h.z + a.z + acc.z + bias[cb + 2];
        float h3 = h.w + a.w + acc.w + bias[cb + 3];
        float z0 = h0 * Wl[(cb + 0) * 2 + 0] + h1 * Wl[(cb + 1) * 2 + 0]
                 + h2 * Wl[(cb + 2) * 2 + 0] + h3 * Wl[(cb + 3) * 2 + 0];
        float z1 = h0 * Wl[(cb + 0) * 2 + 1] + h1 * Wl[(cb + 1) * 2 + 1]
                 + h2 * Wl[(cb + 2) * 2 + 1] + h3 * Wl[(cb + 3) * 2 + 1];
#pragma unroll
        for (int off = 16; off > 0; off >>= 1) {
            z0 += __shfl_xor_sync(0xffffffffu, z0, off);
            z1 += __shfl_xor_sync(0xffffffffu, z1, off);
        }
        if (lane == 0) {
            z0 += bl[0]; z1 += bl[1];
            float m  = fmaxf(z0, z1);
            float ls = logf(expf(z0 - m) + expf(z1 - m));
            Y[(size_t)node * 2 + 0] = z0 - m - ls;
            Y[(size_t)node * 2 + 1] = z1 - m - ls;
        }
    }
}

__global__ void k_tail(const int* __restrict__ ei, float* __restrict__ out, int tail) {
    int i = blockIdx.x * blockDim.x + threadIdx.x;
    if (i >= tail) return;
    out[NN * CCLS + i] = (i < 2 * EE) ? (float)ei[i] : 0.f;
}

// ---------------- launch ----------------
extern "C" void kernel_launch(void* const* d_in, const int* in_sizes, int n_in,
                              void* d_out, int out_size) {
    const float* x  = (const float*)d_in[0];
    const int*   ei = (const int*)d_in[1];
    const float* W1 = (const float*)d_in[2];
    const float* b1 = (const float*)d_in[3];
    const float* W2 = (const float*)d_in[4];
    const float* b2 = (const float*)d_in[5];
    const float* Wl = (const float*)d_in[6];
    const float* bl = (const float*)d_in[7];
    float* out = (float*)d_out;

    float *dDeg, *dA, *dB, *dC, *dHb, *dWc1, *dWc2;
    int   *dCnt;
    cudaGetSymbolAddress((void**)&dDeg, g_deg);
    cudaGetSymbolAddress((void**)&dCnt, g_cnt);
    cudaGetSymbolAddress((void**)&dA,   g_A);
    cudaGetSymbolAddress((void**)&dB,   g_B);
    cudaGetSymbolAddress((void**)&dC,   g_C);
    cudaGetSymbolAddress((void**)&dHb,  g_Hb);
    cudaGetSymbolAddress((void**)&dWc1, g_Wcat1);
    cudaGetSymbolAddress((void**)&dWc2, g_Wcat2);

    // ---- CSR build ----
    k_zero<<<(NN / 4 + 255) / 256, 256>>>(dDeg, NN / 4);
    k_zero<<<(NN / 4 + 255) / 256, 256>>>((float*)dCnt, NN / 4);
    k_deg<<<(EE + 255) / 256, 256>>>(ei);
    k_dinv<<<(NN + 255) / 256, 256>>>();
    k_edgew<<<(EE + 255) / 256, 256>>>();
    k_scanA<<<NB, CHUNK>>>();
    k_scanB<<<1, 256>>>();
    k_scanC<<<NB, CHUNK>>>();
    k_scatter<<<(EE + 255) / 256, 256>>>();

    const int PG = (NN + 7) / 8;
    dim3 gg(6, (NN + 127) / 128);

    // ---- layer 1 ----
    k_wcat<<<(FIN * 384 + 255) / 256, 256>>>(W1, dWc1, FIN);
    k_mma_gemm<<<gg, 256>>>(x, FIN, (FIN + 15) / 16, dWc1, dA, dB, dC);
    k_prop_csr<1><<<PG, 256>>>(dC, dB, nullptr, nullptr, nullptr, nullptr, dB);
    k_prop_csr<2><<<PG, 256>>>(dB, dA, nullptr, b1, nullptr, nullptr, dHb);

    // ---- layer 2 ----
    k_wcat<<<(HH * 384 + 255) / 256, 256>>>(W2, dWc2, HH);
    k_mma_gemm<<<gg, 256>>>(dHb, HH, HH / 16, dWc2, dA, dB, dC);
    k_prop_csr<1><<<PG, 256>>>(dC, dB, nullptr, nullptr, nullptr, nullptr, dB);
    k_prop_csr<3><<<PG, 256>>>(dB, dHb, dA, b2, Wl, bl, out);

    // ---- tail ----
    int tail = out_size - NN * CCLS;
    if (tail > 0)
        k_tail<<<(tail + 255) / 256, 256>>>(ei, out, tail);
}

// round 7
// speedup vs baseline: 1.8568x; 1.8568x over previous
#include <cuda_runtime.h>
#include <cuda_bf16.h>
#include <math.h>
#include <stdint.h>

#define NN    100000
#define NNP   100096                     // NN rounded up to 128
#define EE    1600000
#define FIN   165
#define HH    128
#define CCLS  2
#define CHUNK 512
#define NB    ((NN + CHUNK - 1) / CHUNK)   // 196
#define KP1   176                        // FIN padded to 16
#define NKB1  (KP1 / 16)                 // 11
#define NKB2  (HH / 16)                  // 8

// ---------------- static device scratch (no allocation allowed) ----------------
__device__ __align__(16) float g_deg [NN];
__device__ __align__(16) float g_dinv[NN];
__device__ __align__(16) float g_w   [EE];
__device__ __align__(16) int   g_src [EE];
__device__ __align__(16) int   g_dst [EE];

// CSR (sorted by dst)
__device__ __align__(16) int   g_cnt [NN];
__device__ __align__(16) int   g_tmp [NN];
__device__ __align__(16) int   g_ptr [NN + 1];
__device__ __align__(16) int   g_fill[NN];
__device__ __align__(16) int   g_bsum[NB];
__device__ __align__(16) int   g_boff[NB];
__device__ __align__(16) int   g_esrc[EE];
__device__ __align__(16) float g_ews [EE];

__device__ __align__(16) float g_A [NN * HH];   // x @ (W0 - W2)
__device__ __align__(16) float g_B [NN * HH];   // x @ W1, then B + 2*P(C)
__device__ __align__(16) float g_C [NN * HH];   // x @ W2
__device__ __align__(16) float g_Hb[NN * HH];   // layer-1 activation h

// pre-split bf16 operands: A planes tiled [kb][NNP][16], W planes [n][kpad]
__device__ __align__(16) unsigned short g_XH[NKB1 * NNP * 16];
__device__ __align__(16) unsigned short g_XL[NKB1 * NNP * 16];
__device__ __align__(16) unsigned short g_WH[384 * KP1];
__device__ __align__(16) unsigned short g_WL[384 * KP1];

// ---------------- setup kernels ----------------
__global__ void k_zero(float* __restrict__ p, int n4) {
    int i = blockIdx.x * blockDim.x + threadIdx.x;
    if (i < n4) ((float4*)p)[i] = make_float4(0.f, 0.f, 0.f, 0.f);
}

__global__ void k_deg(const int* __restrict__ ei) {
    int e = blockIdx.x * blockDim.x + threadIdx.x;
    if (e >= EE) return;
    int s = ei[e];
    int d = ei[EE + e];
    if ((unsigned)s >= NN || (unsigned)d >= NN) { s = 0; d = 0; }
    g_src[e] = s;
    g_dst[e] = d;
    if (s != d) atomicAdd(&g_deg[s], 1.0f);
}

__global__ void k_dinv() {
    int i = blockIdx.x * blockDim.x + threadIdx.x;
    if (i >= NN) return;
    float d = g_deg[i];
    g_dinv[i] = (d > 0.f) ? rsqrtf(d) : 0.f;
}

__global__ void k_edgew() {
    int e = blockIdx.x * blockDim.x + threadIdx.x;
    if (e >= EE) return;
    int s = g_src[e], d = g_dst[e];
    float w = (s != d) ? (-g_dinv[s] * g_dinv[d]) : 0.f;
    g_w[e] = w;
    if (w != 0.f) atomicAdd(&g_cnt[d], 1);
}

__global__ void k_scanA() {
    __shared__ int s[CHUNK];
    int i = blockIdx.x * CHUNK + threadIdx.x;
    int v = (i < NN) ? g_cnt[i] : 0;
    s[threadIdx.x] = v;
    __syncthreads();
    for (int off = 1; off < CHUNK; off <<= 1) {
        int t = (threadIdx.x >= off) ? s[threadIdx.x - off] : 0;
        __syncthreads();
        s[threadIdx.x] += t;
        __syncthreads();
    }
    if (i < NN) g_tmp[i] = s[threadIdx.x];
    if (threadIdx.x == CHUNK - 1) g_bsum[blockIdx.x] = s[CHUNK - 1];
}

__global__ void k_scanB() {
    __shared__ int s[256];
    int v = (threadIdx.x < NB) ? g_bsum[threadIdx.x] : 0;
    s[threadIdx.x] = v;
    __syncthreads();
    for (int off = 1; off < 256; off <<= 1) {
        int t = (threadIdx.x >= off) ? s[threadIdx.x - off] : 0;
        __syncthreads();
        s[threadIdx.x] += t;
        __syncthreads();
    }
    if (threadIdx.x < NB) g_boff[threadIdx.x] = s[threadIdx.x] - v;
    if (threadIdx.x == NB - 1) g_ptr[NN] = s[threadIdx.x];
}

__global__ void k_scanC() {
    int i = blockIdx.x * CHUNK + threadIdx.x;
    if (i >= NN) return;
    int excl = g_boff[blockIdx.x] + g_tmp[i] - g_cnt[i];
    g_ptr[i]  = excl;
    g_fill[i] = excl;
}

__global__ void k_scatter() {
    int e = blockIdx.x * blockDim.x + threadIdx.x;
    if (e >= EE) return;
    float w = g_w[e];
    if (w == 0.f) return;
    int pos = atomicAdd(&g_fill[g_dst[e]], 1);
    g_esrc[pos] = g_src[e];
    g_ews[pos]  = w;
}

// Wcat = [W0 - W2 | W1 | W2] pre-split to bf16 hi/lo, layout [n(384)][kpad]
__global__ void k_wcat(const float* __restrict__ W, int kdim, int kpad) {
    int idx = blockIdx.x * blockDim.x + threadIdx.x;
    if (idx >= 384 * kpad) return;
    int c = idx / kpad;            // output column 0..383
    int f = idx - c * kpad;        // k index
    float v = 0.f;
    if (f < kdim) {
        if (c < HH)            v = W[f * HH + c] - W[2 * kdim * HH + f * HH + c];
        else if (c < 2 * HH)   v = W[kdim * HH + f * HH + (c - HH)];
        else                   v = W[2 * kdim * HH + f * HH + (c - 2 * HH)];
    }
    __nv_bfloat16 hi = __float2bfloat16_rn(v);
    __nv_bfloat16 lo = __float2bfloat16_rn(v - __bfloat162float(hi));
    g_WH[idx] = *(unsigned short*)&hi;
    g_WL[idx] = *(unsigned short*)&lo;
}

// Split X[NN x kreal] -> bf16 hi/lo planes, tiled [kb][NNP][16]
__global__ void k_split(const float* __restrict__ X, int kreal, int nkb) {
    int idx = blockIdx.x * blockDim.x + threadIdx.x;
    if (idx >= NN * nkb) return;
    int row = idx / nkb;
    int kb  = idx - row * nkb;
    unsigned short h[16], l[16];
#pragma unroll
    for (int j = 0; j < 16; j++) {
        int gk = kb * 16 + j;
        float v = (gk < kreal) ? X[(size_t)row * kreal + gk] : 0.f;
        __nv_bfloat16 hb = __float2bfloat16_rn(v);
        __nv_bfloat16 lb = __float2bfloat16_rn(v - __bfloat162float(hb));
        h[j] = *(unsigned short*)&hb;
        l[j] = *(unsigned short*)&lb;
    }
    size_t base = ((size_t)kb * NNP + row) * 16;
    ((uint4*)(g_XH + base))[0] = ((uint4*)h)[0];
    ((uint4*)(g_XH + base))[1] = ((uint4*)h)[1];
    ((uint4*)(g_XL + base))[0] = ((uint4*)l)[0];
    ((uint4*)(g_XL + base))[1] = ((uint4*)l)[1];
}

// ---------------- bf16x3 tensor-core GEMM (pre-split operands, pure LDS+MMA loop) ----------------
#define MMA_BF16(d, a0, a1, a2, a3, b0, b1) \
    asm volatile("mma.sync.aligned.m16n8k16.row.col.f32.bf16.bf16.f32 " \
        "{%0,%1,%2,%3}, {%4,%5,%6,%7}, {%8,%9}, {%0,%1,%2,%3};" \
        : "+f"((d)[0]), "+f"((d)[1]), "+f"((d)[2]), "+f"((d)[3]) \
        : "r"(a0), "r"(a1), "r"(a2), "r"(a3), "r"(b0), "r"(b1))

// C[N x 384] = X @ Wcat, CTA tile 128x64, grid (6, NNP/128). 3 passes: hh + hl + lh.
__global__ void __launch_bounds__(256) k_gemm_bf16(
        int nkb, int kpad,
        float* __restrict__ o0, float* __restrict__ o1, float* __restrict__ o2) {
    __shared__ unsigned short AsH[128 * 16], AsL[128 * 16];
    __shared__ unsigned short BsH[64 * 16],  BsL[64 * 16];

    int tid  = threadIdx.x;
    int wid  = tid >> 5;
    int lane = tid & 31;
    int wm   = wid >> 1;          // 0..3 : 32-row strip
    int wn   = wid & 1;           // 0..1 : 32-col strip
    int g    = lane >> 2;         // 0..7
    int t    = lane & 3;          // 0..3

    int nb   = blockIdx.x;        // 0..5
    int row0 = blockIdx.y * 128;
    int n0   = nb * 64;

    float acc[2][4][4];
#pragma unroll
    for (int mi = 0; mi < 2; mi++)
#pragma unroll
        for (int ni = 0; ni < 4; ni++)
#pragma unroll
            for (int j = 0; j < 4; j++) acc[mi][ni][j] = 0.f;

    for (int kb = 0; kb < nkb; kb++) {
        // A tiles: fully contiguous 4KB each
        {
            size_t base = ((size_t)kb * NNP + row0) * 16;
            ((uint4*)AsH)[tid] = *(const uint4*)(g_XH + base + tid * 8);
            ((uint4*)AsL)[tid] = *(const uint4*)(g_XL + base + tid * 8);
        }
        // B tiles: 64 rows x 32B
        {
            int nn = tid >> 2, j = tid & 3;
            size_t src = (size_t)(n0 + nn) * kpad + kb * 16 + j * 4;
            ((uint2*)BsH)[tid] = *(const uint2*)(g_WH + src);
            ((uint2*)BsL)[tid] = *(const uint2*)(g_WL + src);
        }
        __syncthreads();

        uint32_t ah[2][4], al[2][4], bh[4][2], bl[4][2];
#pragma unroll
        for (int mi = 0; mi < 2; mi++) {
            int rb = wm * 32 + mi * 16;
            ah[mi][0] = *(uint32_t*)(AsH + (rb + g    ) * 16 + 2 * t);
            ah[mi][1] = *(uint32_t*)(AsH + (rb + g + 8) * 16 + 2 * t);
            ah[mi][2] = *(uint32_t*)(AsH + (rb + g    ) * 16 + 2 * t + 8);
            ah[mi][3] = *(uint32_t*)(AsH + (rb + g + 8) * 16 + 2 * t + 8);
            al[mi][0] = *(uint32_t*)(AsL + (rb + g    ) * 16 + 2 * t);
            al[mi][1] = *(uint32_t*)(AsL + (rb + g + 8) * 16 + 2 * t);
            al[mi][2] = *(uint32_t*)(AsL + (rb + g    ) * 16 + 2 * t + 8);
            al[mi][3] = *(uint32_t*)(AsL + (rb + g + 8) * 16 + 2 * t + 8);
        }
#pragma unroll
        for (int ni = 0; ni < 4; ni++) {
            int nc = wn * 32 + ni * 8 + g;
            bh[ni][0] = *(uint32_t*)(BsH + nc * 16 + 2 * t);
            bh[ni][1] = *(uint32_t*)(BsH + nc * 16 + 2 * t + 8);
            bl[ni][0] = *(uint32_t*)(BsL + nc * 16 + 2 * t);
            bl[ni][1] = *(uint32_t*)(BsL + nc * 16 + 2 * t + 8);
        }
        __syncthreads();

#pragma unroll
        for (int mi = 0; mi < 2; mi++)
#pragma unroll
            for (int ni = 0; ni < 4; ni++) {
                MMA_BF16(acc[mi][ni], ah[mi][0], ah[mi][1], ah[mi][2], ah[mi][3],
                         bh[ni][0], bh[ni][1]);
                MMA_BF16(acc[mi][ni], ah[mi][0], ah[mi][1], ah[mi][2], ah[mi][3],
                         bl[ni][0], bl[ni][1]);
                MMA_BF16(acc[mi][ni], al[mi][0], al[mi][1], al[mi][2], al[mi][3],
                         bh[ni][0], bh[ni][1]);
            }
    }

    float* O = (nb < 2) ? o0 : ((nb < 4) ? o1 : o2);
    int cbase = (nb & 1) * 64 + wn * 32;
#pragma unroll
    for (int mi = 0; mi < 2; mi++) {
        int r = row0 + wm * 32 + mi * 16 + g;
#pragma unroll
        for (int ni = 0; ni < 4; ni++) {
            int c = cbase + ni * 8 + t * 2;
            if (r < NN)
                *(float2*)(O + (size_t)r * HH + c) = make_float2(acc[mi][ni][0], acc[mi][ni][1]);
            if (r + 8 < NN)
                *(float2*)(O + (size_t)(r + 8) * HH + c) = make_float2(acc[mi][ni][2], acc[mi][ni][3]);
        }
    }
}

// ---------------- CSR prop, one warp per node, fused epilogues ----------------
template <int MODE>
__global__ void __launch_bounds__(256) k_prop_csr(
        const float* __restrict__ X,
        const float* __restrict__ P0, const float* __restrict__ P1,
        const float* __restrict__ bias,
        const float* __restrict__ Wl, const float* __restrict__ bl,
        float* __restrict__ Y) {
    int node = blockIdx.x * 8 + (threadIdx.x >> 5);
    if (node >= NN) return;
    int lane = threadIdx.x & 31;
    int beg = g_ptr[node], end = g_ptr[node + 1];

    float4 acc = make_float4(0.f, 0.f, 0.f, 0.f);
#pragma unroll 4
    for (int i = beg; i < end; i++) {
        int   s  = g_esrc[i];
        float wt = g_ews[i];
        float4 v = *(const float4*)(X + (size_t)s * HH + lane * 4);
        acc.x += wt * v.x; acc.y += wt * v.y;
        acc.z += wt * v.z; acc.w += wt * v.w;
    }

    size_t o  = (size_t)node * 32 + lane;
    int    cb = lane * 4;

    if (MODE == 1) {
        float4 b = ((const float4*)P0)[o];
        b.x += 2.f * acc.x; b.y += 2.f * acc.y;
        b.z += 2.f * acc.z; b.w += 2.f * acc.w;
        ((float4*)Y)[o] = b;
    } else if (MODE == 2) {
        float4 a = ((const float4*)P0)[o];
        a.x = fmaxf(a.x + acc.x + bias[cb + 0], 0.f);
        a.y = fmaxf(a.y + acc.y + bias[cb + 1], 0.f);
        a.z = fmaxf(a.z + acc.z + bias[cb + 2], 0.f);
        a.w = fmaxf(a.w + acc.w + bias[cb + 3], 0.f);
        ((float4*)Y)[o] = a;
    } else {
        float4 h = ((const float4*)P0)[o];
        float4 a = ((const float4*)P1)[o];
        float h0 = h.x + a.x + acc.x + bias[cb + 0];
        float h1 = h.y + a.y + acc.y + bias[cb + 1];
        float h2 = h.z + a.z + acc.z + bias[cb + 2];
        float h3 = h.w + a.w + acc.w + bias[cb + 3];
        float z0 = h0 * Wl[(cb + 0) * 2 + 0] + h1 * Wl[(cb + 1) * 2 + 0]
                 + h2 * Wl[(cb + 2) * 2 + 0] + h3 * Wl[(cb + 3) * 2 + 0];
        float z1 = h0 * Wl[(cb + 0) * 2 + 1] + h1 * Wl[(cb + 1) * 2 + 1]
                 + h2 * Wl[(cb + 2) * 2 + 1] + h3 * Wl[(cb + 3) * 2 + 1];
#pragma unroll
        for (int off = 16; off > 0; off >>= 1) {
            z0 += __shfl_xor_sync(0xffffffffu, z0, off);
            z1 += __shfl_xor_sync(0xffffffffu, z1, off);
        }
        if (lane == 0) {
            z0 += bl[0]; z1 += bl[1];
            float m  = fmaxf(z0, z1);
            float ls = logf(expf(z0 - m) + expf(z1 - m));
            Y[(size_t)node * 2 + 0] = z0 - m - ls;
            Y[(size_t)node * 2 + 1] = z1 - m - ls;
        }
    }
}

__global__ void k_tail(const int* __restrict__ ei, float* __restrict__ out, int tail) {
    int i = blockIdx.x * blockDim.x + threadIdx.x;
    if (i >= tail) return;
    out[NN * CCLS + i] = (i < 2 * EE) ? (float)ei[i] : 0.f;
}

// ---------------- launch ----------------
extern "C" void kernel_launch(void* const* d_in, const int* in_sizes, int n_in,
                              void* d_out, int out_size) {
    const float* x  = (const float*)d_in[0];
    const int*   ei = (const int*)d_in[1];
    const float* W1 = (const float*)d_in[2];
    const float* b1 = (const float*)d_in[3];
    const float* W2 = (const float*)d_in[4];
    const float* b2 = (const float*)d_in[5];
    const float* Wl = (const float*)d_in[6];
    const float* bl = (const float*)d_in[7];
    float* out = (float*)d_out;

    float *dDeg, *dA, *dB, *dC, *dHb;
    int   *dCnt;
    cudaGetSymbolAddress((void**)&dDeg, g_deg);
    cudaGetSymbolAddress((void**)&dCnt, g_cnt);
    cudaGetSymbolAddress((void**)&dA,   g_A);
    cudaGetSymbolAddress((void**)&dB,   g_B);
    cudaGetSymbolAddress((void**)&dC,   g_C);
    cudaGetSymbolAddress((void**)&dHb,  g_Hb);

    // ---- CSR build ----
    k_zero<<<(NN / 4 + 255) / 256, 256>>>(dDeg, NN / 4);
    k_zero<<<(NN / 4 + 255) / 256, 256>>>((float*)dCnt, NN / 4);
    k_deg<<<(EE + 255) / 256, 256>>>(ei);
    k_dinv<<<(NN + 255) / 256, 256>>>();
    k_edgew<<<(EE + 255) / 256, 256>>>();
    k_scanA<<<NB, CHUNK>>>();
    k_scanB<<<1, 256>>>();
    k_scanC<<<NB, CHUNK>>>();
    k_scatter<<<(EE + 255) / 256, 256>>>();

    const int PG = (NN + 7) / 8;
    dim3 gg(6, NNP / 128);

    // ---- layer 1 ----
    k_wcat<<<(384 * KP1 + 255) / 256, 256>>>(W1, FIN, KP1);
    k_split<<<(NN * NKB1 + 255) / 256, 256>>>(x, FIN, NKB1);
    k_gemm_bf16<<<gg, 256>>>(NKB1, KP1, dA, dB, dC);
    k_prop_csr<1><<<PG, 256>>>(dC, dB, nullptr, nullptr, nullptr, nullptr, dB);
    k_prop_csr<2><<<PG, 256>>>(dB, dA, nullptr, b1, nullptr, nullptr, dHb);

    // ---- layer 2 ----
    k_wcat<<<(384 * HH + 255) / 256, 256>>>(W2, HH, HH);
    k_split<<<(NN * NKB2 + 255) / 256, 256>>>(dHb, HH, NKB2);
    k_gemm_bf16<<<gg, 256>>>(NKB2, HH, dA, dB, dC);
    k_prop_csr<1><<<PG, 256>>>(dC, dB, nullptr, nullptr, nullptr, nullptr, dB);
    k_prop_csr<3><<<PG, 256>>>(dB, dHb, dA, b2, Wl, bl, out);

    // ---- tail ----
    int tail = out_size - NN * CCLS;
    if (tail > 0)
        k_tail<<<(tail + 255) / 256, 256>>>(ei, out, tail);
}

// round 8
// speedup vs baseline: 2.1137x; 1.1383x over previous
#include <cuda_runtime.h>
#include <cuda_bf16.h>
#include <cuda_fp16.h>
#include <math.h>
#include <stdint.h>

#define NN    100000
#define NNP   100096                     // NN rounded up to 128
#define EE    1600000
#define FIN   165
#define HH    128
#define CCLS  2
#define CHUNK 512
#define NB    ((NN + CHUNK - 1) / CHUNK)   // 196
#define KP1   176                        // FIN padded to 16
#define NKB1  (KP1 / 16)                 // 11
#define NKB2  (HH / 16)                  // 8

// ---------------- static device scratch (no allocation allowed) ----------------
__device__ __align__(16) int   g_degi[NN];
__device__ __align__(16) float g_dinv[NN];
__device__ __align__(16) int   g_src [EE];
__device__ __align__(16) int   g_dst [EE];

// CSR (sorted by dst)
__device__ __align__(16) int   g_cnt [NN];
__device__ __align__(16) int   g_tmp [NN];
__device__ __align__(16) int   g_ptr [NN + 1];
__device__ __align__(16) int   g_fill[NN];
__device__ __align__(16) int   g_bsum[NB];
__device__ __align__(16) int   g_boff[NB];
__device__ __align__(16) int   g_esrc[EE];
__device__ __align__(16) float g_ews [EE];

__device__ __align__(16) float g_A [NN * HH];   // x @ (W0 - W2)  (fp32 stream)
__device__ __align__(16) float g_B [NN * HH];   // x @ W1         (fp32 stream)
__device__ __align__(16) float g_Hb[NN * HH];   // layer-1 activation (fp32)
__device__ __align__(16) unsigned short g_C16[NN * HH];  // x @ W2 (fp16, gather-only)
__device__ __align__(16) unsigned short g_B16[NN * HH];  // B + 2P(C) (fp16, gather-only)

// pre-split bf16 GEMM operands: A planes tiled [kb][NNP][16], W planes [n][kpad]
__device__ __align__(16) unsigned short g_XH[NKB1 * NNP * 16];
__device__ __align__(16) unsigned short g_XL[NKB1 * NNP * 16];
__device__ __align__(16) unsigned short g_WH[384 * KP1];
__device__ __align__(16) unsigned short g_WL[384 * KP1];

// ---------------- setup kernels ----------------
__global__ void k_zero(float* __restrict__ p, int n4) {
    int i = blockIdx.x * blockDim.x + threadIdx.x;
    if (i < n4) ((float4*)p)[i] = make_float4(0.f, 0.f, 0.f, 0.f);
}

// edge decode + both degree histograms (src out-degree, dst in-degree for CSR)
__global__ void k_deg(const int* __restrict__ ei) {
    int e = blockIdx.x * blockDim.x + threadIdx.x;
    if (e >= EE) return;
    int s = ei[e];
    int d = ei[EE + e];
    if ((unsigned)s >= NN || (unsigned)d >= NN) { s = 0; d = 0; }
    g_src[e] = s;
    g_dst[e] = d;
    if (s != d) {
        atomicAdd(&g_degi[s], 1);
        atomicAdd(&g_cnt[d], 1);
    }
}

__global__ void k_dinv() {
    int i = blockIdx.x * blockDim.x + threadIdx.x;
    if (i >= NN) return;
    int d = g_degi[i];
    g_dinv[i] = (d > 0) ? rsqrtf((float)d) : 0.f;
}

__global__ void k_scanA() {
    __shared__ int s[CHUNK];
    int i = blockIdx.x * CHUNK + threadIdx.x;
    int v = (i < NN) ? g_cnt[i] : 0;
    s[threadIdx.x] = v;
    __syncthreads();
    for (int off = 1; off < CHUNK; off <<= 1) {
        int t = (threadIdx.x >= off) ? s[threadIdx.x - off] : 0;
        __syncthreads();
        s[threadIdx.x] += t;
        __syncthreads();
    }
    if (i < NN) g_tmp[i] = s[threadIdx.x];
    if (threadIdx.x == CHUNK - 1) g_bsum[blockIdx.x] = s[CHUNK - 1];
}

__global__ void k_scanB() {
    __shared__ int s[256];
    int v = (threadIdx.x < NB) ? g_bsum[threadIdx.x] : 0;
    s[threadIdx.x] = v;
    __syncthreads();
    for (int off = 1; off < 256; off <<= 1) {
        int t = (threadIdx.x >= off) ? s[threadIdx.x - off] : 0;
        __syncthreads();
        s[threadIdx.x] += t;
        __syncthreads();
    }
    if (threadIdx.x < NB) g_boff[threadIdx.x] = s[threadIdx.x] - v;
    if (threadIdx.x == NB - 1) g_ptr[NN] = s[threadIdx.x];
}

__global__ void k_scanC() {
    int i = blockIdx.x * CHUNK + threadIdx.x;
    if (i >= NN) return;
    int excl = g_boff[blockIdx.x] + g_tmp[i] - g_cnt[i];
    g_ptr[i]  = excl;
    g_fill[i] = excl;
}

// scatter with inline weight computation (k_edgew folded in)
__global__ void k_scatter() {
    int e = blockIdx.x * blockDim.x + threadIdx.x;
    if (e >= EE) return;
    int s = g_src[e], d = g_dst[e];
    if (s == d) return;
    int pos = atomicAdd(&g_fill[d], 1);
    g_esrc[pos] = s;
    g_ews[pos]  = -g_dinv[s] * g_dinv[d];
}

// Wcat = [W0 - W2 | W1 | W2] pre-split to bf16 hi/lo, layout [n(384)][kpad]
__global__ void k_wcat(const float* __restrict__ W, int kdim, int kpad) {
    int idx = blockIdx.x * blockDim.x + threadIdx.x;
    if (idx >= 384 * kpad) return;
    int c = idx / kpad;
    int f = idx - c * kpad;
    float v = 0.f;
    if (f < kdim) {
        if (c < HH)            v = W[f * HH + c] - W[2 * kdim * HH + f * HH + c];
        else if (c < 2 * HH)   v = W[kdim * HH + f * HH + (c - HH)];
        else                   v = W[2 * kdim * HH + f * HH + (c - 2 * HH)];
    }
    __nv_bfloat16 hi = __float2bfloat16_rn(v);
    __nv_bfloat16 lo = __float2bfloat16_rn(v - __bfloat162float(hi));
    g_WH[idx] = *(unsigned short*)&hi;
    g_WL[idx] = *(unsigned short*)&lo;
}

// Split X[NN x kreal] -> bf16 hi/lo planes, tiled [kb][NNP][16] (layer-1 input only)
__global__ void k_split(const float* __restrict__ X, int kreal, int nkb) {
    int idx = blockIdx.x * blockDim.x + threadIdx.x;
    if (idx >= NN * nkb) return;
    int row = idx / nkb;
    int kb  = idx - row * nkb;
    unsigned short h[16], l[16];
#pragma unroll
    for (int j = 0; j < 16; j++) {
        int gk = kb * 16 + j;
        float v = (gk < kreal) ? X[(size_t)row * kreal + gk] : 0.f;
        __nv_bfloat16 hb = __float2bfloat16_rn(v);
        __nv_bfloat16 lb = __float2bfloat16_rn(v - __bfloat162float(hb));
        h[j] = *(unsigned short*)&hb;
        l[j] = *(unsigned short*)&lb;
    }
    size_t base = ((size_t)kb * NNP + row) * 16;
    ((uint4*)(g_XH + base))[0] = ((uint4*)h)[0];
    ((uint4*)(g_XH + base))[1] = ((uint4*)h)[1];
    ((uint4*)(g_XL + base))[0] = ((uint4*)l)[0];
    ((uint4*)(g_XL + base))[1] = ((uint4*)l)[1];
}

// ---------------- bf16x3 tensor-core GEMM ----------------
#define MMA_BF16(d, a0, a1, a2, a3, b0, b1) \
    asm volatile("mma.sync.aligned.m16n8k16.row.col.f32.bf16.bf16.f32 " \
        "{%0,%1,%2,%3}, {%4,%5,%6,%7}, {%8,%9}, {%0,%1,%2,%3};" \
        : "+f"((d)[0]), "+f"((d)[1]), "+f"((d)[2]), "+f"((d)[3]) \
        : "r"(a0), "r"(a1), "r"(a2), "r"(a3), "r"(b0), "r"(b1))

// C[N x 384] = X @ Wcat. Cols [0,128)->o0 fp32, [128,256)->o1 fp32, [256,384)->c16 fp16.
__global__ void __launch_bounds__(256) k_gemm_bf16(
        int nkb, int kpad,
        float* __restrict__ o0, float* __restrict__ o1, unsigned short* __restrict__ c16) {
    __shared__ unsigned short AsH[128 * 16], AsL[128 * 16];
    __shared__ unsigned short BsH[64 * 16],  BsL[64 * 16];

    int tid  = threadIdx.x;
    int wid  = tid >> 5;
    int lane = tid & 31;
    int wm   = wid >> 1;
    int wn   = wid & 1;
    int g    = lane >> 2;
    int t    = lane & 3;

    int nb   = blockIdx.x;        // 0..5
    int row0 = blockIdx.y * 128;
    int n0   = nb * 64;

    float acc[2][4][4];
#pragma unroll
    for (int mi = 0; mi < 2; mi++)
#pragma unroll
        for (int ni = 0; ni < 4; ni++)
#pragma unroll
            for (int j = 0; j < 4; j++) acc[mi][ni][j] = 0.f;

    for (int kb = 0; kb < nkb; kb++) {
        {
            size_t base = ((size_t)kb * NNP + row0) * 16;
            ((uint4*)AsH)[tid] = *(const uint4*)(g_XH + base + tid * 8);
            ((uint4*)AsL)[tid] = *(const uint4*)(g_XL + base + tid * 8);
        }
        {
            int nn = tid >> 2, j = tid & 3;
            size_t src = (size_t)(n0 + nn) * kpad + kb * 16 + j * 4;
            ((uint2*)BsH)[tid] = *(const uint2*)(g_WH + src);
            ((uint2*)BsL)[tid] = *(const uint2*)(g_WL + src);
        }
        __syncthreads();

        uint32_t ah[2][4], al[2][4], bh[4][2], bl[4][2];
#pragma unroll
        for (int mi = 0; mi < 2; mi++) {
            int rb = wm * 32 + mi * 16;
            ah[mi][0] = *(uint32_t*)(AsH + (rb + g    ) * 16 + 2 * t);
            ah[mi][1] = *(uint32_t*)(AsH + (rb + g + 8) * 16 + 2 * t);
            ah[mi][2] = *(uint32_t*)(AsH + (rb + g    ) * 16 + 2 * t + 8);
            ah[mi][3] = *(uint32_t*)(AsH + (rb + g + 8) * 16 + 2 * t + 8);
            al[mi][0] = *(uint32_t*)(AsL + (rb + g    ) * 16 + 2 * t);
            al[mi][1] = *(uint32_t*)(AsL + (rb + g + 8) * 16 + 2 * t);
            al[mi][2] = *(uint32_t*)(AsL + (rb + g    ) * 16 + 2 * t + 8);
            al[mi][3] = *(uint32_t*)(AsL + (rb + g + 8) * 16 + 2 * t + 8);
        }
#pragma unroll
        for (int ni = 0; ni < 4; ni++) {
            int nc = wn * 32 + ni * 8 + g;
            bh[ni][0] = *(uint32_t*)(BsH + nc * 16 + 2 * t);
            bh[ni][1] = *(uint32_t*)(BsH + nc * 16 + 2 * t + 8);
            bl[ni][0] = *(uint32_t*)(BsL + nc * 16 + 2 * t);
            bl[ni][1] = *(uint32_t*)(BsL + nc * 16 + 2 * t + 8);
        }
        __syncthreads();

#pragma unroll
        for (int mi = 0; mi < 2; mi++)
#pragma unroll
            for (int ni = 0; ni < 4; ni++) {
                MMA_BF16(acc[mi][ni], ah[mi][0], ah[mi][1], ah[mi][2], ah[mi][3],
                         bh[ni][0], bh[ni][1]);
                MMA_BF16(acc[mi][ni], ah[mi][0], ah[mi][1], ah[mi][2], ah[mi][3],
                         bl[ni][0], bl[ni][1]);
                MMA_BF16(acc[mi][ni], al[mi][0], al[mi][1], al[mi][2], al[mi][3],
                         bh[ni][0], bh[ni][1]);
            }
    }

    int cbase = (nb & 1) * 64 + wn * 32;
    if (nb < 4) {
        float* O = (nb < 2) ? o0 : o1;
#pragma unroll
        for (int mi = 0; mi < 2; mi++) {
            int r = row0 + wm * 32 + mi * 16 + g;
#pragma unroll
            for (int ni = 0; ni < 4; ni++) {
                int c = cbase + ni * 8 + t * 2;
                if (r < NN)
                    *(float2*)(O + (size_t)r * HH + c) = make_float2(acc[mi][ni][0], acc[mi][ni][1]);
                if (r + 8 < NN)
                    *(float2*)(O + (size_t)(r + 8) * HH + c) = make_float2(acc[mi][ni][2], acc[mi][ni][3]);
            }
        }
    } else {
        // C part -> fp16 (gather-only consumer)
#pragma unroll
        for (int mi = 0; mi < 2; mi++) {
            int r = row0 + wm * 32 + mi * 16 + g;
#pragma unroll
            for (int ni = 0; ni < 4; ni++) {
                int c = cbase + ni * 8 + t * 2;
                if (r < NN) {
                    __half2 v = __floats2half2_rn(acc[mi][ni][0], acc[mi][ni][1]);
                    *(uint32_t*)(c16 + (size_t)r * HH + c) = *(uint32_t*)&v;
                }
                if (r + 8 < NN) {
                    __half2 v = __floats2half2_rn(acc[mi][ni][2], acc[mi][ni][3]);
                    *(uint32_t*)(c16 + (size_t)(r + 8) * HH + c) = *(uint32_t*)&v;
                }
            }
        }
    }
}

// ---------------- CSR prop (fp16 gather), one warp per node, fused epilogues ----------------
// MODE 1: Yh = P0 + 2*acc (fp16)            [gather C16, stream B fp32]
// MODE 2: Hb = relu(P0 + acc + bias) (fp32) + emit bf16 hi/lo planes for GEMM-2
// MODE 3: h = P0 + P1 + acc + bias; logits -> log_softmax -> Yf
template <int MODE>
__global__ void __launch_bounds__(256) k_prop_csr(
        const unsigned short* __restrict__ X16,
        const float* __restrict__ P0, const float* __restrict__ P1,
        const float* __restrict__ bias,
        const float* __restrict__ Wl, const float* __restrict__ bl,
        float* __restrict__ Yf, unsigned short* __restrict__ Yh) {
    int node = blockIdx.x * 8 + (threadIdx.x >> 5);
    if (node >= NN) return;
    int lane = threadIdx.x & 31;
    int beg = g_ptr[node], end = g_ptr[node + 1];

    float4 acc = make_float4(0.f, 0.f, 0.f, 0.f);
#pragma unroll 4
    for (int i = beg; i < end; i++) {
        int   s  = g_esrc[i];
        float wt = g_ews[i];
        uint2 raw = *(const uint2*)(X16 + (size_t)s * HH + lane * 4);
        float2 f01 = __half22float2(*(__half2*)&raw.x);
        float2 f23 = __half22float2(*(__half2*)&raw.y);
        acc.x += wt * f01.x; acc.y += wt * f01.y;
        acc.z += wt * f23.x; acc.w += wt * f23.y;
    }

    size_t o  = (size_t)node * 32 + lane;
    int    cb = lane * 4;

    if (MODE == 1) {
        float4 b = ((const float4*)P0)[o];
        b.x += 2.f * acc.x; b.y += 2.f * acc.y;
        b.z += 2.f * acc.z; b.w += 2.f * acc.w;
        __half2 v0 = __floats2half2_rn(b.x, b.y);
        __half2 v1 = __floats2half2_rn(b.z, b.w);
        uint2 pk;
        pk.x = *(uint32_t*)&v0;
        pk.y = *(uint32_t*)&v1;
        *(uint2*)(Yh + (size_t)node * HH + cb) = pk;
    } else if (MODE == 2) {
        float4 a = ((const float4*)P0)[o];
        a.x = fmaxf(a.x + acc.x + bias[cb + 0], 0.f);
        a.y = fmaxf(a.y + acc.y + bias[cb + 1], 0.f);
        a.z = fmaxf(a.z + acc.z + bias[cb + 2], 0.f);
        a.w = fmaxf(a.w + acc.w + bias[cb + 3], 0.f);
        ((float4*)Yf)[o] = a;
        // fused bf16 hi/lo split for layer-2 GEMM: layout [kb][NNP][16]
        float v[4] = {a.x, a.y, a.z, a.w};
        unsigned short h4[4], l4[4];
#pragma unroll
        for (int j = 0; j < 4; j++) {
            __nv_bfloat16 hb = __float2bfloat16_rn(v[j]);
            __nv_bfloat16 lb = __float2bfloat16_rn(v[j] - __bfloat162float(hb));
            h4[j] = *(unsigned short*)&hb;
            l4[j] = *(unsigned short*)&lb;
        }
        int kb = lane >> 2;
        int jb = (lane & 3) * 4;
        size_t base = ((size_t)kb * NNP + node) * 16 + jb;
        *(uint2*)(g_XH + base) = *(uint2*)h4;
        *(uint2*)(g_XL + base) = *(uint2*)l4;
    } else {
        float4 h = ((const float4*)P0)[o];
        float4 a = ((const float4*)P1)[o];
        float h0 = h.x + a.x + acc.x + bias[cb + 0];
        float h1 = h.y + a.y + acc.y + bias[cb + 1];
        float h2 = h.z + a.z + acc.z + bias[cb + 2];
        float h3 = h.w + a.w + acc.w + bias[cb + 3];
        float z0 = h0 * Wl[(cb + 0) * 2 + 0] + h1 * Wl[(cb + 1) * 2 + 0]
                 + h2 * Wl[(cb + 2) * 2 + 0] + h3 * Wl[(cb + 3) * 2 + 0];
        float z1 = h0 * Wl[(cb + 0) * 2 + 1] + h1 * Wl[(cb + 1) * 2 + 1]
                 + h2 * Wl[(cb + 2) * 2 + 1] + h3 * Wl[(cb + 3) * 2 + 1];
#pragma unroll
        for (int off = 16; off > 0; off >>= 1) {
            z0 += __shfl_xor_sync(0xffffffffu, z0, off);
            z1 += __shfl_xor_sync(0xffffffffu, z1, off);
        }
        if (lane == 0) {
            z0 += bl[0]; z1 += bl[1];
            float m  = fmaxf(z0, z1);
            float ls = logf(expf(z0 - m) + expf(z1 - m));
            Yf[(size_t)node * 2 + 0] = z0 - m - ls;
            Yf[(size_t)node * 2 + 1] = z1 - m - ls;
        }
    }
}

__global__ void k_tail(const int* __restrict__ ei, float* __restrict__ out, int tail) {
    int i = blockIdx.x * blockDim.x + threadIdx.x;
    if (i >= tail) return;
    out[NN * CCLS + i] = (i < 2 * EE) ? (float)ei[i] : 0.f;
}

// ---------------- launch ----------------
extern "C" void kernel_launch(void* const* d_in, const int* in_sizes, int n_in,
                              void* d_out, int out_size) {
    const float* x  = (const float*)d_in[0];
    const int*   ei = (const int*)d_in[1];
    const float* W1 = (const float*)d_in[2];
    const float* b1 = (const float*)d_in[3];
    const float* W2 = (const float*)d_in[4];
    const float* b2 = (const float*)d_in[5];
    const float* Wl = (const float*)d_in[6];
    const float* bl = (const float*)d_in[7];
    float* out = (float*)d_out;

    float *dA, *dB, *dHb;
    int *dDegi, *dCnt;
    unsigned short *dC16, *dB16;
    cudaGetSymbolAddress((void**)&dDegi, g_degi);
    cudaGetSymbolAddress((void**)&dCnt,  g_cnt);
    cudaGetSymbolAddress((void**)&dA,    g_A);
    cudaGetSymbolAddress((void**)&dB,    g_B);
    cudaGetSymbolAddress((void**)&dHb,   g_Hb);
    cudaGetSymbolAddress((void**)&dC16,  g_C16);
    cudaGetSymbolAddress((void**)&dB16,  g_B16);

    // ---- CSR build ----
    k_zero<<<(NN / 4 + 255) / 256, 256>>>((float*)dDegi, NN / 4);
    k_zero<<<(NN / 4 + 255) / 256, 256>>>((float*)dCnt, NN / 4);
    k_deg<<<(EE + 255) / 256, 256>>>(ei);
    k_dinv<<<(NN + 255) / 256, 256>>>();
    k_scanA<<<NB, CHUNK>>>();
    k_scanB<<<1, 256>>>();
    k_scanC<<<NB, CHUNK>>>();
    k_scatter<<<(EE + 255) / 256, 256>>>();

    const int PG = (NN + 7) / 8;
    dim3 gg(6, NNP / 128);

    // ---- layer 1 ----
    k_wcat<<<(384 * KP1 + 255) / 256, 256>>>(W1, FIN, KP1);
    k_split<<<(NN * NKB1 + 255) / 256, 256>>>(x, FIN, NKB1);
    k_gemm_bf16<<<gg, 256>>>(NKB1, KP1, dA, dB, dC16);
    k_prop_csr<1><<<PG, 256>>>(dC16, dB, nullptr, nullptr, nullptr, nullptr, nullptr, dB16);
    k_prop_csr<2><<<PG, 256>>>(dB16, dA, nullptr, b1, nullptr, nullptr, dHb, nullptr);

    // ---- layer 2 (Hb's bf16 planes were emitted by MODE2) ----
    k_wcat<<<(384 * HH + 255) / 256, 256>>>(W2, HH, HH);
    k_gemm_bf16<<<gg, 256>>>(NKB2, HH, dA, dB, dC16);
    k_prop_csr<1><<<PG, 256>>>(dC16, dB, nullptr, nullptr, nullptr, nullptr, nullptr, dB16);
    k_prop_csr<3><<<PG, 256>>>(dB16, dHb, dA, b2, Wl, bl, out, nullptr);

    // ---- tail ----
    int tail = out_size - NN * CCLS;
    if (tail > 0)
        k_tail<<<(tail + 255) / 256, 256>>>(ei, out, tail);
}

// round 12
// speedup vs baseline: 2.1703x; 1.0268x over previous
#include <cuda_runtime.h>
#include <cuda_bf16.h>
#include <cuda_fp16.h>
#include <math.h>
#include <stdint.h>

#define NN    100000
#define NNP   100096                     // NN rounded up to 128
#define EE    1600000
#define FIN   165
#define HH    128
#define CCLS  2
#define CHUNK 512
#define NB    ((NN + CHUNK - 1) / CHUNK)   // 196
#define KP1   176                        // FIN padded to 16
#define NKB1  (KP1 / 16)                 // 11
#define NKB2  (HH / 16)                  // 8

// ---------------- static device scratch (no allocation allowed) ----------------
__device__ __align__(16) int   g_degi[NN];
__device__ __align__(16) float g_dinv[NN];
__device__ __align__(16) int   g_src [EE];
__device__ __align__(16) int   g_dst [EE];

// CSR (sorted by dst), packed (src, weight) records
__device__ __align__(16) int   g_cnt [NN];
__device__ __align__(16) int   g_tmp [NN];
__device__ __align__(16) int   g_ptr [NN + 1];
__device__ __align__(16) int   g_fill[NN];
__device__ __align__(16) int   g_bsum[NB];
__device__ __align__(16) int   g_boff[NB];
__device__ __align__(16) int2  g_epack[EE];

__device__ __align__(16) float g_A [NN * HH];   // x @ (W0 - W2)  (fp32 stream)
__device__ __align__(16) float g_B [NN * HH];   // x @ W1         (fp32 stream)
__device__ __align__(16) float g_Hb[NN * HH];   // layer-1 activation (fp32)
__device__ __align__(16) unsigned short g_C16[NN * HH];  // x @ W2 (fp16, gather-only)
__device__ __align__(16) unsigned short g_B16[NN * HH];  // B + 2P(C) (fp16, gather-only)

// pre-split bf16 GEMM operands: A planes tiled [kb][NNP][16], W planes [n][kpad]
__device__ __align__(16) unsigned short g_XH[NKB1 * NNP * 16];
__device__ __align__(16) unsigned short g_XL[NKB1 * NNP * 16];
__device__ __align__(16) unsigned short g_WH[384 * KP1];
__device__ __align__(16) unsigned short g_WL[384 * KP1];

// ---------------- setup kernels ----------------
__global__ void k_zero2(int* __restrict__ p, int n, int* __restrict__ q, int m) {
    int i = blockIdx.x * blockDim.x + threadIdx.x;
    if (i < n) p[i] = 0;
    if (i < m) q[i] = 0;
}

// edge decode (2 edges/thread) + both degree histograms
__global__ void k_deg(const int* __restrict__ ei) {
    int e2 = blockIdx.x * blockDim.x + threadIdx.x;
    if (e2 >= EE / 2) return;
    int2 ss = ((const int2*)ei)[e2];
    int2 dd = ((const int2*)(ei + EE))[e2];
    if ((unsigned)ss.x >= NN || (unsigned)dd.x >= NN) { ss.x = 0; dd.x = 0; }
    if ((unsigned)ss.y >= NN || (unsigned)dd.y >= NN) { ss.y = 0; dd.y = 0; }
    ((int2*)g_src)[e2] = ss;
    ((int2*)g_dst)[e2] = dd;
    if (ss.x != dd.x) { atomicAdd(&g_degi[ss.x], 1); atomicAdd(&g_cnt[dd.x], 1); }
    if (ss.y != dd.y) { atomicAdd(&g_degi[ss.y], 1); atomicAdd(&g_cnt[dd.y], 1); }
}

__global__ void k_scanA() {
    __shared__ int s[CHUNK];
    int i = blockIdx.x * CHUNK + threadIdx.x;
    int v = (i < NN) ? g_cnt[i] : 0;
    s[threadIdx.x] = v;
    __syncthreads();
    for (int off = 1; off < CHUNK; off <<= 1) {
        int t = (threadIdx.x >= off) ? s[threadIdx.x - off] : 0;
        __syncthreads();
        s[threadIdx.x] += t;
        __syncthreads();
    }
    if (i < NN) g_tmp[i] = s[threadIdx.x];
    if (threadIdx.x == CHUNK - 1) g_bsum[blockIdx.x] = s[CHUNK - 1];
}

__global__ void k_scanB() {
    __shared__ int s[256];
    int v = (threadIdx.x < NB) ? g_bsum[threadIdx.x] : 0;
    s[threadIdx.x] = v;
    __syncthreads();
    for (int off = 1; off < 256; off <<= 1) {
        int t = (threadIdx.x >= off) ? s[threadIdx.x - off] : 0;
        __syncthreads();
        s[threadIdx.x] += t;
        __syncthreads();
    }
    if (threadIdx.x < NB) g_boff[threadIdx.x] = s[threadIdx.x] - v;
    if (threadIdx.x == NB - 1) g_ptr[NN] = s[threadIdx.x];
}

// scanC + dinv fused
__global__ void k_scanC() {
    int i = blockIdx.x * CHUNK + threadIdx.x;
    if (i >= NN) return;
    int excl = g_boff[blockIdx.x] + g_tmp[i] - g_cnt[i];
    g_ptr[i]  = excl;
    g_fill[i] = excl;
    int d = g_degi[i];
    g_dinv[i] = (d > 0) ? rsqrtf((float)d) : 0.f;
}

// scatter packed (src, weight) with inline weight computation
__global__ void k_scatter() {
    int e = blockIdx.x * blockDim.x + threadIdx.x;
    if (e >= EE) return;
    int s = g_src[e], d = g_dst[e];
    if (s == d) return;
    int pos = atomicAdd(&g_fill[d], 1);
    float w = -g_dinv[s] * g_dinv[d];
    g_epack[pos] = make_int2(s, __float_as_int(w));
}

// Wcat = [W0 - W2 | W1 | W2] pre-split to bf16 hi/lo, layout [n(384)][kpad]
__global__ void k_wcat(const float* __restrict__ W, int kdim, int kpad) {
    int idx = blockIdx.x * blockDim.x + threadIdx.x;
    if (idx >= 384 * kpad) return;
    int c = idx / kpad;
    int f = idx - c * kpad;
    float v = 0.f;
    if (f < kdim) {
        if (c < HH)            v = W[f * HH + c] - W[2 * kdim * HH + f * HH + c];
        else if (c < 2 * HH)   v = W[kdim * HH + f * HH + (c - HH)];
        else                   v = W[2 * kdim * HH + f * HH + (c - 2 * HH)];
    }
    __nv_bfloat16 hi = __float2bfloat16_rn(v);
    __nv_bfloat16 lo = __float2bfloat16_rn(v - __bfloat162float(hi));
    g_WH[idx] = *(unsigned short*)&hi;
    g_WL[idx] = *(unsigned short*)&lo;
}

// Split X[NN x kreal] -> bf16 hi/lo planes, tiled [kb][NNP][16] (layer-1 input only)
__global__ void k_split(const float* __restrict__ X, int kreal, int nkb) {
    int idx = blockIdx.x * blockDim.x + threadIdx.x;
    if (idx >= NN * nkb) return;
    int row = idx / nkb;
    int kb  = idx - row * nkb;
    unsigned short h[16], l[16];
#pragma unroll
    for (int j = 0; j < 16; j++) {
        int gk = kb * 16 + j;
        float v = (gk < kreal) ? X[(size_t)row * kreal + gk] : 0.f;
        __nv_bfloat16 hb = __float2bfloat16_rn(v);
        __nv_bfloat16 lb = __float2bfloat16_rn(v - __bfloat162float(hb));
        h[j] = *(unsigned short*)&hb;
        l[j] = *(unsigned short*)&lb;
    }
    size_t base = ((size_t)kb * NNP + row) * 16;
    ((uint4*)(g_XH + base))[0] = ((uint4*)h)[0];
    ((uint4*)(g_XH + base))[1] = ((uint4*)h)[1];
    ((uint4*)(g_XL + base))[0] = ((uint4*)l)[0];
    ((uint4*)(g_XL + base))[1] = ((uint4*)l)[1];
}

// ---------------- bf16x3 tensor-core GEMM, double-buffered mainloop ----------------
#define MMA_BF16(d, a0, a1, a2, a3, b0, b1) \
    asm volatile("mma.sync.aligned.m16n8k16.row.col.f32.bf16.bf16.f32 " \
        "{%0,%1,%2,%3}, {%4,%5,%6,%7}, {%8,%9}, {%0,%1,%2,%3};" \
        : "+f"((d)[0]), "+f"((d)[1]), "+f"((d)[2]), "+f"((d)[3]) \
        : "r"(a0), "r"(a1), "r"(a2), "r"(a3), "r"(b0), "r"(b1))

__global__ void __launch_bounds__(256) k_gemm_bf16(
        int nkb, int kpad,
        float* __restrict__ o0, float* __restrict__ o1, unsigned short* __restrict__ c16) {
    __shared__ unsigned short AsH[2][128 * 16], AsL[2][128 * 16];
    __shared__ unsigned short BsH[2][64 * 16],  BsL[2][64 * 16];

    int tid  = threadIdx.x;
    int wid  = tid >> 5;
    int lane = tid & 31;
    int wm   = wid >> 1;
    int wn   = wid & 1;
    int g    = lane >> 2;
    int t    = lane & 3;

    int nb   = blockIdx.x;        // 0..5
    int row0 = blockIdx.y * 128;
    int n0   = nb * 64;

    int bnn = tid >> 2, bj = tid & 3;   // B-tile load coords

    float acc[2][4][4];
#pragma unroll
    for (int mi = 0; mi < 2; mi++)
#pragma unroll
        for (int ni = 0; ni < 4; ni++)
#pragma unroll
            for (int j = 0; j < 4; j++) acc[mi][ni][j] = 0.f;

    // prologue: fill buffer 0
    {
        size_t base = ((size_t)row0) * 16;
        ((uint4*)AsH[0])[tid] = *(const uint4*)(g_XH + base + tid * 8);
        ((uint4*)AsL[0])[tid] = *(const uint4*)(g_XL + base + tid * 8);
        size_t src = (size_t)(n0 + bnn) * kpad + bj * 4;
        ((uint2*)BsH[0])[tid] = *(const uint2*)(g_WH + src);
        ((uint2*)BsL[0])[tid] = *(const uint2*)(g_WL + src);
    }
    __syncthreads();

    for (int kb = 0; kb < nkb; kb++) {
        int cur = kb & 1, nxt = cur ^ 1;
        // prefetch next k-block into registers (hidden under MMA)
        uint4 pah, pal; uint2 pbh, pbl;
        if (kb + 1 < nkb) {
            size_t base = ((size_t)(kb + 1) * NNP + row0) * 16;
            pah = *(const uint4*)(g_XH + base + tid * 8);
            pal = *(const uint4*)(g_XL + base + tid * 8);
            size_t src = (size_t)(n0 + bnn) * kpad + (kb + 1) * 16 + bj * 4;
            pbh = *(const uint2*)(g_WH + src);
            pbl = *(const uint2*)(g_WL + src);
        }

        uint32_t ah[2][4], al[2][4], bh[4][2], bl[4][2];
#pragma unroll
        for (int mi = 0; mi < 2; mi++) {
            int rb = wm * 32 + mi * 16;
            ah[mi][0] = *(uint32_t*)(AsH[cur] + (rb + g    ) * 16 + 2 * t);
            ah[mi][1] = *(uint32_t*)(AsH[cur] + (rb + g + 8) * 16 + 2 * t);
            ah[mi][2] = *(uint32_t*)(AsH[cur] + (rb + g    ) * 16 + 2 * t + 8);
            ah[mi][3] = *(uint32_t*)(AsH[cur] + (rb + g + 8) * 16 + 2 * t + 8);
            al[mi][0] = *(uint32_t*)(AsL[cur] + (rb + g    ) * 16 + 2 * t);
            al[mi][1] = *(uint32_t*)(AsL[cur] + (rb + g + 8) * 16 + 2 * t);
            al[mi][2] = *(uint32_t*)(AsL[cur] + (rb + g    ) * 16 + 2 * t + 8);
            al[mi][3] = *(uint32_t*)(AsL[cur] + (rb + g + 8) * 16 + 2 * t + 8);
        }
#pragma unroll
        for (int ni = 0; ni < 4; ni++) {
            int nc = wn * 32 + ni * 8 + g;
            bh[ni][0] = *(uint32_t*)(BsH[cur] + nc * 16 + 2 * t);
            bh[ni][1] = *(uint32_t*)(BsH[cur] + nc * 16 + 2 * t + 8);
            bl[ni][0] = *(uint32_t*)(BsL[cur] + nc * 16 + 2 * t);
            bl[ni][1] = *(uint32_t*)(BsL[cur] + nc * 16 + 2 * t + 8);
        }

#pragma unroll
        for (int mi = 0; mi < 2; mi++)
#pragma unroll
            for (int ni = 0; ni < 4; ni++) {
                MMA_BF16(acc[mi][ni], ah[mi][0], ah[mi][1], ah[mi][2], ah[mi][3],
                         bh[ni][0], bh[ni][1]);
                MMA_BF16(acc[mi][ni], ah[mi][0], ah[mi][1], ah[mi][2], ah[mi][3],
                         bl[ni][0], bl[ni][1]);
                MMA_BF16(acc[mi][ni], al[mi][0], al[mi][1], al[mi][2], al[mi][3],
                         bh[ni][0], bh[ni][1]);
            }

        if (kb + 1 < nkb) {
            ((uint4*)AsH[nxt])[tid] = pah;
            ((uint4*)AsL[nxt])[tid] = pal;
            ((uint2*)BsH[nxt])[tid] = pbh;
            ((uint2*)BsL[nxt])[tid] = pbl;
            __syncthreads();
        }
    }

    int cbase = (nb & 1) * 64 + wn * 32;
    if (nb < 4) {
        float* O = (nb < 2) ? o0 : o1;
#pragma unroll
        for (int mi = 0; mi < 2; mi++) {
            int r = row0 + wm * 32 + mi * 16 + g;
#pragma unroll
            for (int ni = 0; ni < 4; ni++) {
                int c = cbase + ni * 8 + t * 2;
                if (r < NN)
                    *(float2*)(O + (size_t)r * HH + c) = make_float2(acc[mi][ni][0], acc[mi][ni][1]);
                if (r + 8 < NN)
                    *(float2*)(O + (size_t)(r + 8) * HH + c) = make_float2(acc[mi][ni][2], acc[mi][ni][3]);
            }
        }
    } else {
#pragma unroll
        for (int mi = 0; mi < 2; mi++) {
            int r = row0 + wm * 32 + mi * 16 + g;
#pragma unroll
            for (int ni = 0; ni < 4; ni++) {
                int c = cbase + ni * 8 + t * 2;
                if (r < NN) {
                    __half2 v = __floats2half2_rn(acc[mi][ni][0], acc[mi][ni][1]);
                    *(uint32_t*)(c16 + (size_t)r * HH + c) = *(uint32_t*)&v;
                }
                if (r + 8 < NN) {
                    __half2 v = __floats2half2_rn(acc[mi][ni][2], acc[mi][ni][3]);
                    *(uint32_t*)(c16 + (size_t)(r + 8) * HH + c) = *(uint32_t*)&v;
                }
            }
        }
    }
}

// ---------------- CSR prop (fp16 gather, packed edges), fused epilogues ----------------
template <int MODE>
__global__ void __launch_bounds__(256) k_prop_csr(
        const unsigned short* __restrict__ X16,
        const float* __restrict__ P0, const float* __restrict__ P1,
        const float* __restrict__ bias,
        const float* __restrict__ Wl, const float* __restrict__ bl,
        float* __restrict__ Yf, unsigned short* __restrict__ Yh) {
    int node = blockIdx.x * 8 + (threadIdx.x >> 5);
    if (node >= NN) return;
    int lane = threadIdx.x & 31;
    int beg = g_ptr[node], end = g_ptr[node + 1];

    float4 acc = make_float4(0.f, 0.f, 0.f, 0.f);
#pragma unroll 4
    for (int i = beg; i < end; i++) {
        int2  pk = g_epack[i];
        float wt = __int_as_float(pk.y);
        uint2 raw = *(const uint2*)(X16 + (size_t)pk.x * HH + lane * 4);
        float2 f01 = __half22float2(*(__half2*)&raw.x);
        float2 f23 = __half22float2(*(__half2*)&raw.y);
        acc.x += wt * f01.x; acc.y += wt * f01.y;
        acc.z += wt * f23.x; acc.w += wt * f23.y;
    }

    size_t o  = (size_t)node * 32 + lane;
    int    cb = lane * 4;

    if (MODE == 1) {
        float4 b = ((const float4*)P0)[o];
        b.x += 2.f * acc.x; b.y += 2.f * acc.y;
        b.z += 2.f * acc.z; b.w += 2.f * acc.w;
        __half2 v0 = __floats2half2_rn(b.x, b.y);
        __half2 v1 = __floats2half2_rn(b.z, b.w);
        uint2 pk2;
        pk2.x = *(uint32_t*)&v0;
        pk2.y = *(uint32_t*)&v1;
        *(uint2*)(Yh + (size_t)node * HH + cb) = pk2;
    } else if (MODE == 2) {
        float4 a = ((const float4*)P0)[o];
        a.x = fmaxf(a.x + acc.x + bias[cb + 0], 0.f);
        a.y = fmaxf(a.y + acc.y + bias[cb + 1], 0.f);
        a.z = fmaxf(a.z + acc.z + bias[cb + 2], 0.f);
        a.w = fmaxf(a.w + acc.w + bias[cb + 3], 0.f);
        ((float4*)Yf)[o] = a;
        float v[4] = {a.x, a.y, a.z, a.w};
        unsigned short h4[4], l4[4];
#pragma unroll
        for (int j = 0; j < 4; j++) {
            __nv_bfloat16 hb = __float2bfloat16_rn(v[j]);
            __nv_bfloat16 lb = __float2bfloat16_rn(v[j] - __bfloat162float(hb));
            h4[j] = *(unsigned short*)&hb;
            l4[j] = *(unsigned short*)&lb;
        }
        int kb = lane >> 2;
        int jb = (lane & 3) * 4;
        size_t base = ((size_t)kb * NNP + node) * 16 + jb;
        *(uint2*)(g_XH + base) = *(uint2*)h4;
        *(uint2*)(g_XL + base) = *(uint2*)l4;
    } else {
        float4 h = ((const float4*)P0)[o];
        float4 a = ((const float4*)P1)[o];
        float h0 = h.x + a.x + acc.x + bias[cb + 0];
        float h1 = h.y + a.y + acc.y + bias[cb + 1];
        float h2 = h.z + a.z + acc.z + bias[cb + 2];
        float h3 = h.w + a.w + acc.w + bias[cb + 3];
        float z0 = h0 * Wl[(cb + 0) * 2 + 0] + h1 * Wl[(cb + 1) * 2 + 0]
                 + h2 * Wl[(cb + 2) * 2 + 0] + h3 * Wl[(cb + 3) * 2 + 0];
        float z1 = h0 * Wl[(cb + 0) * 2 + 1] + h1 * Wl[(cb + 1) * 2 + 1]
                 + h2 * Wl[(cb + 2) * 2 + 1] + h3 * Wl[(cb + 3) * 2 + 1];
#pragma unroll
        for (int off = 16; off > 0; off >>= 1) {
            z0 += __shfl_xor_sync(0xffffffffu, z0, off);
            z1 += __shfl_xor_sync(0xffffffffu, z1, off);
        }
        if (lane == 0) {
            z0 += bl[0]; z1 += bl[1];
            float m  = fmaxf(z0, z1);
            float ls = logf(expf(z0 - m) + expf(z1 - m));
            Yf[(size_t)node * 2 + 0] = z0 - m - ls;
            Yf[(size_t)node * 2 + 1] = z1 - m - ls;
        }
    }
}

__global__ void k_tail(const int* __restrict__ ei, float* __restrict__ out, int tail) {
    int i = blockIdx.x * blockDim.x + threadIdx.x;
    if (i >= tail) return;
    out[NN * CCLS + i] = (i < 2 * EE) ? (float)ei[i] : 0.f;
}

// ---------------- launch ----------------
extern "C" void kernel_launch(void* const* d_in, const int* in_sizes, int n_in,
                              void* d_out, int out_size) {
    const float* x  = (const float*)d_in[0];
    const int*   ei = (const int*)d_in[1];
    const float* W1 = (const float*)d_in[2];
    const float* b1 = (const float*)d_in[3];
    const float* W2 = (const float*)d_in[4];
    const float* b2 = (const float*)d_in[5];
    const float* Wl = (const float*)d_in[6];
    const float* bl = (const float*)d_in[7];
    float* out = (float*)d_out;

    float *dA, *dB, *dHb;
    int *dDegi, *dCnt;
    unsigned short *dC16, *dB16;
    cudaGetSymbolAddress((void**)&dDegi, g_degi);
    cudaGetSymbolAddress((void**)&dCnt,  g_cnt);
    cudaGetSymbolAddress((void**)&dA,    g_A);
    cudaGetSymbolAddress((void**)&dB,    g_B);
    cudaGetSymbolAddress((void**)&dHb,   g_Hb);
    cudaGetSymbolAddress((void**)&dC16,  g_C16);
    cudaGetSymbolAddress((void**)&dB16,  g_B16);

    const int PG = (NN + 7) / 8;
    dim3 gg(6, NNP / 128);

    // #1..#3: layer-1 GEMM prerequisites (so launch #4 = GEMM1 for ncu)
    k_wcat<<<(384 * KP1 + 255) / 256, 256>>>(W1, FIN, KP1);
    k_split<<<(NN * NKB1 + 255) / 256, 256>>>(x, FIN, NKB1);
    k_zero2<<<(NN + 255) / 256, 256>>>(dDegi, NN, dCnt, NN);

    // #4: layer-1 GEMM (profiled launch)
    k_gemm_bf16<<<gg, 256>>>(NKB1, KP1, dA, dB, dC16);

    // #5..#9: CSR build
    k_deg<<<(EE / 2 + 255) / 256, 256>>>(ei);
    k_scanA<<<NB, CHUNK>>>();
    k_scanB<<<1, 256>>>();
    k_scanC<<<NB, CHUNK>>>();
    k_scatter<<<(EE + 255) / 256, 256>>>();

    // layer-1 props
    k_prop_csr<1><<<PG, 256>>>(dC16, dB, nullptr, nullptr, nullptr, nullptr, nullptr, dB16);
    k_prop_csr<2><<<PG, 256>>>(dB16, dA, nullptr, b1, nullptr, nullptr, dHb, nullptr);

    // layer 2 (Hb bf16 planes emitted by MODE2)
    k_wcat<<<(384 * HH + 255) / 256, 256>>>(W2, HH, HH);
    k_gemm_bf16<<<gg, 256>>>(NKB2, HH, dA, dB, dC16);
    k_prop_csr<1><<<PG, 256>>>(dC16, dB, nullptr, nullptr, nullptr, nullptr, nullptr, dB16);
    k_prop_csr<3><<<PG, 256>>>(dB16, dHb, dA, b2, Wl, bl, out, nullptr);

    // tail
    int tail = out_size - NN * CCLS;
    if (tail > 0)
        k_tail<<<(tail + 255) / 256, 256>>>(ei, out, tail);
}